// round 15
// baseline (speedup 1.0000x reference)
#include <cuda_runtime.h>
#include <mma.h>
#include <math.h>

using namespace nvcuda;

#define B_    256
#define NH    6
#define NT    343
#define NTP   352               // 343 padded to 22*16
#define HD    32
#define CDIM  192
#define MROWS (B_*NT)           // 87808 = 343*256
#define QSCALE 0.17677669529663687f

// ---------------- scratch (device globals; no allocation allowed) -----------
__device__ float g_q[(size_t)B_*NH*NT*HD];
__device__ float g_k[(size_t)B_*NH*NT*HD];
__device__ float g_v[(size_t)B_*NH*NT*HD];
__device__ float g_ao[(size_t)MROWS*CDIM];
__device__ float g_bias[(size_t)NH*NT*NT];

#define CVT_FRAG(f) do { _Pragma("unroll") \
    for (int _e = 0; _e < (f).num_elements; _e++) \
        (f).x[_e] = wmma::__float_to_tf32((f).x[_e]); } while (0)

// ---------------- bias materialization --------------------------------------
__global__ void bias_kernel(const float* __restrict__ table,
                            const int*   __restrict__ ridx) {
    int i = blockIdx.x * blockDim.x + threadIdx.x;
    if (i >= NT*NT) return;
    int idx = ridx[i];
    #pragma unroll
    for (int h = 0; h < NH; h++)
        g_bias[(size_t)h*NT*NT + i] = table[idx*NH + h];
}

// ---------------- tf32 WMMA GEMM: C[M,Nc] = A[M,192] @ W[Nc,192]^T + bias ----
// BM=256 x BN=64, 8 warps each 32x64 (2x4 frags), BKC=32 double-buffered,
// one __syncthreads per chunk. MODE 0 scatters qkv; MODE 1 writes d_out.
#define GBM 256
#define GBN 64
#define GKC 32
#define AST 36
#define BST 36
#define CST 20
#define GEMM_SMEM_FLOATS (2*GBM*AST + 2*GBN*BST + 8*16*CST)

template<int MODE>
__global__ void __launch_bounds__(256)
gemm_tc(const float* __restrict__ A_in,
        const float* __restrict__ W,
        const float* __restrict__ bias,
        float*       __restrict__ out) {
    extern __shared__ float smg[];
    float* As = smg;                     // [2][GBM*AST]
    float* Bs = As + 2 * GBM * AST;      // [2][GBN*BST]
    float* Cs = Bs + 2 * GBN * BST;      // [8][16*CST]

    const float* __restrict__ A = (MODE == 0) ? A_in : g_ao;
    const int t    = threadIdx.x;
    const int warp = t >> 5;
    const int lane = t & 31;
    const int m0 = blockIdx.y * GBM;
    const int n0 = blockIdx.x * GBN;

    // global staging pointers: thread t owns A row (m0+t), k cols [k0,k0+32)
    // and W row n0+(t>>2), k cols k0+(t&3)*8 + [0,8)
    const float* pa = &A[(size_t)(m0 + t) * CDIM];
    const float* pb = &W[(size_t)(n0 + (t >> 2)) * CDIM + (t & 3) * 8];
    float* asr = &As[0];   // stage written via offset
    const int aoff = t * AST;
    const int boff = (t >> 2) * BST + (t & 3) * 8;

    wmma::fragment<wmma::accumulator, 16, 16, 8, float> acc[2][4];
    #pragma unroll
    for (int i = 0; i < 2; i++)
        #pragma unroll
        for (int j = 0; j < 4; j++)
            wmma::fill_fragment(acc[i][j], 0.0f);

    // prologue: stage chunk 0
    {
        #pragma unroll
        for (int u = 0; u < 8; u++)
            *(float4*)&As[aoff + u * 4] = *(const float4*)(pa + u * 4);
        *(float4*)&Bs[boff]     = *(const float4*)(pb);
        *(float4*)&Bs[boff + 4] = *(const float4*)(pb + 4);
    }
    __syncthreads();

    int stage = 0;
    for (int k0 = 0; k0 < CDIM; k0 += GKC) {
        float4 ra[8], rb[2];
        const bool has_next = (k0 + GKC < CDIM);
        if (has_next) {
            #pragma unroll
            for (int u = 0; u < 8; u++)
                ra[u] = *(const float4*)(pa + k0 + GKC + u * 4);
            rb[0] = *(const float4*)(pb + k0 + GKC);
            rb[1] = *(const float4*)(pb + k0 + GKC + 4);
        }

        const float* as = &As[stage * GBM * AST + warp * 32 * AST];
        const float* bs = &Bs[stage * GBN * BST];
        #pragma unroll
        for (int kk = 0; kk < GKC; kk += 8) {
            wmma::fragment<wmma::matrix_a, 16, 16, 8, wmma::precision::tf32,
                           wmma::row_major> a0, a1;
            wmma::load_matrix_sync(a0, as + kk, AST);
            wmma::load_matrix_sync(a1, as + 16 * AST + kk, AST);
            CVT_FRAG(a0); CVT_FRAG(a1);
            #pragma unroll
            for (int j = 0; j < 4; j++) {
                wmma::fragment<wmma::matrix_b, 16, 16, 8, wmma::precision::tf32,
                               wmma::col_major> bf;
                wmma::load_matrix_sync(bf, bs + (j * 16) * BST + kk, BST);
                CVT_FRAG(bf);
                wmma::mma_sync(acc[0][j], a0, bf, acc[0][j]);
                wmma::mma_sync(acc[1][j], a1, bf, acc[1][j]);
            }
        }

        if (has_next) {
            const int ns = stage ^ 1;
            float* ad = &As[ns * GBM * AST + aoff];
            float* bd = &Bs[ns * GBN * BST + boff];
            #pragma unroll
            for (int u = 0; u < 8; u++)
                *(float4*)(ad + u * 4) = ra[u];
            *(float4*)(bd)     = rb[0];
            *(float4*)(bd + 4) = rb[1];
            __syncthreads();
        }
        stage ^= 1;
    }

    // epilogue: stage frags through per-warp smem patch, bias + store/scatter
    float* cw = &Cs[warp * 16 * CST];
    #pragma unroll
    for (int i = 0; i < 2; i++) {
        #pragma unroll
        for (int j = 0; j < 4; j++) {
            wmma::store_matrix_sync(cw, acc[i][j], CST, wmma::mem_row_major);
            __syncwarp();
            #pragma unroll
            for (int e = 0; e < 8; e++) {
                int idx = lane * 8 + e;          // 0..255
                int row = idx >> 4, col = idx & 15;
                int m = m0 + warp * 32 + i * 16 + row;
                int cc = n0 + j * 16 + col;
                float v = cw[row * CST + col] + bias[cc];
                if (MODE == 0) {
                    int bb = m / NT, n = m - bb * NT;
                    int s = cc / CDIM;
                    int hc = cc - s * CDIM;
                    int h = hc >> 5, d = hc & 31;
                    size_t dst = ((size_t)(bb * NH + h) * NT + n) * HD + d;
                    if      (s == 0) g_q[dst] = v * QSCALE;
                    else if (s == 1) g_k[dst] = v;
                    else             g_v[dst] = v;
                } else {
                    out[(size_t)m * CDIM + cc] = v;
                }
            }
            __syncwarp();
        }
    }
}

// ---------------- attention: tf32 WMMA, one CTA per (b,h) (R14 proven) ------
#define KS2 36
#define SST 356
#define QB  64
#define AT_SMEM_FLOATS (2*NTP*KS2 + QB*SST + QB*KS2 + 8*16*20)

__global__ void __launch_bounds__(256) attn_tc_kernel() {
    extern __shared__ float sm[];
    float* ks = sm;                       // [NTP][KS2]
    float* vs = ks + NTP * KS2;           // [NTP][KS2]
    float* ss = vs + NTP * KS2;           // [QB][SST]
    float* qs = ss + QB * SST;            // [QB][KS2]
    float* os = qs + QB * KS2;            // [8][320]

    const int bh = blockIdx.x;            // 0..1535
    const int b  = bh / NH, h = bh % NH;
    const size_t base = (size_t)bh * NT * HD;
    const int t = threadIdx.x, warp = t >> 5, lane = t & 31;

    for (int i = t; i < (NTP - NT) * KS2; i += 256) {
        int r = NT + i / KS2, c = i % KS2;
        ks[r * KS2 + c] = 0.f;
        vs[r * KS2 + c] = 0.f;
    }
    for (int i = t; i < NT * HD / 4; i += 256) {
        int e = i * 4;
        int j = e >> 5, d = e & 31;
        *(float4*)&ks[j * KS2 + d] = *(const float4*)&g_k[base + e];
        *(float4*)&vs[j * KS2 + d] = *(const float4*)&g_v[base + e];
    }
    __syncthreads();

    const float* __restrict__ bm = &g_bias[(size_t)h * NT * NT];

    for (int qb = 0; qb < NT; qb += QB) {
        for (int i = t; i < QB * HD / 4; i += 256) {
            int e = i * 4;
            int r = e >> 5, d = e & 31;
            int gr = qb + r;
            float4 v = (gr < NT) ? *(const float4*)&g_q[base + (size_t)gr * HD + d]
                                 : make_float4(0.f, 0.f, 0.f, 0.f);
            *(float4*)&qs[r * KS2 + d] = v;
        }
        __syncthreads();

        // ---- S = Q @ K^T ----
        {
            int rt = warp & 3;
            int c0 = (warp >> 2) * 11;
            wmma::fragment<wmma::matrix_a, 16, 16, 8, wmma::precision::tf32,
                           wmma::row_major> a[4];
            #pragma unroll
            for (int kk = 0; kk < 4; kk++) {
                wmma::load_matrix_sync(a[kk], &qs[rt * 16 * KS2 + kk * 8], KS2);
                CVT_FRAG(a[kk]);
            }
            for (int ct = c0; ct < c0 + 11; ct++) {
                wmma::fragment<wmma::accumulator, 16, 16, 8, float> acc;
                wmma::fill_fragment(acc, 0.0f);
                #pragma unroll
                for (int kk = 0; kk < 4; kk++) {
                    wmma::fragment<wmma::matrix_b, 16, 16, 8, wmma::precision::tf32,
                                   wmma::col_major> bf;
                    wmma::load_matrix_sync(bf, &ks[ct * 16 * KS2 + kk * 8], KS2);
                    CVT_FRAG(bf);
                    wmma::mma_sync(acc, a[kk], bf, acc);
                }
                wmma::store_matrix_sync(&ss[rt * 16 * SST + ct * 16], acc, SST,
                                        wmma::mem_row_major);
            }
        }
        __syncthreads();

        // ---- softmax rows ----
        for (int rl = warp * 8; rl < warp * 8 + 8; rl++) {
            int r = qb + rl;
            if (r >= NT) break;
            float* srow = &ss[rl * SST];
            const float* brow = &bm[(size_t)r * NT];
            float v[11];
            float mx = -1e30f;
            #pragma unroll
            for (int tt = 0; tt < 11; tt++) {
                int j = tt * 32 + lane;
                float s = (j < NT) ? srow[j] + brow[j] : -1e30f;
                v[tt] = s;
                mx = fmaxf(mx, s);
            }
            #pragma unroll
            for (int o = 16; o; o >>= 1)
                mx = fmaxf(mx, __shfl_xor_sync(0xffffffffu, mx, o));
            float sum = 0.f;
            #pragma unroll
            for (int tt = 0; tt < 11; tt++) {
                int j = tt * 32 + lane;
                if (j < NT) { float e = __expf(v[tt] - mx); v[tt] = e; sum += e; }
                else v[tt] = 0.f;
            }
            #pragma unroll
            for (int o = 16; o; o >>= 1)
                sum += __shfl_xor_sync(0xffffffffu, sum, o);
            float inv = __frcp_rn(sum);
            #pragma unroll
            for (int tt = 0; tt < 11; tt++) {
                int j = tt * 32 + lane;
                srow[j] = v[tt] * inv;
            }
        }
        __syncthreads();

        // ---- O = P @ V ----
        {
            int rt = warp & 3, ct = warp >> 2;
            wmma::fragment<wmma::accumulator, 16, 16, 8, float> acc0, acc1;
            wmma::fill_fragment(acc0, 0.0f);
            wmma::fill_fragment(acc1, 0.0f);
            #pragma unroll 4
            for (int kk = 0; kk < NTP / 8; kk += 2) {
                wmma::fragment<wmma::matrix_a, 16, 16, 8, wmma::precision::tf32,
                               wmma::row_major> pa, pb;
                wmma::fragment<wmma::matrix_b, 16, 16, 8, wmma::precision::tf32,
                               wmma::row_major> va, vb;
                wmma::load_matrix_sync(pa, &ss[rt * 16 * SST + kk * 8], SST);
                wmma::load_matrix_sync(va, &vs[kk * 8 * KS2 + ct * 16], KS2);
                CVT_FRAG(pa); CVT_FRAG(va);
                wmma::mma_sync(acc0, pa, va, acc0);
                wmma::load_matrix_sync(pb, &ss[rt * 16 * SST + (kk + 1) * 8], SST);
                wmma::load_matrix_sync(vb, &vs[(kk + 1) * 8 * KS2 + ct * 16], KS2);
                CVT_FRAG(pb); CVT_FRAG(vb);
                wmma::mma_sync(acc1, pb, vb, acc1);
            }
            #pragma unroll
            for (int e = 0; e < acc0.num_elements; e++)
                acc0.x[e] += acc1.x[e];
            wmma::store_matrix_sync(&os[warp * 320], acc0, 20, wmma::mem_row_major);
            __syncwarp();
            #pragma unroll
            for (int e = 0; e < 8; e++) {
                int idx = lane * 8 + e;
                int row = idx >> 4, col = idx & 15;
                int r = qb + rt * 16 + row;
                if (r < NT)
                    g_ao[((size_t)b * NT + r) * CDIM + h * HD + ct * 16 + col] =
                        os[warp * 320 + row * 20 + col];
            }
        }
        __syncthreads();
    }
}

// ---------------- launch ----------------------------------------------------
extern "C" void kernel_launch(void* const* d_in, const int* in_sizes, int n_in,
                              void* d_out, int out_size) {
    const float* x      = (const float*)d_in[0];
    const float* w_qkv  = (const float*)d_in[1];
    const float* b_qkv  = (const float*)d_in[2];
    const float* w_proj = (const float*)d_in[3];
    const float* b_proj = (const float*)d_in[4];
    const float* table  = (const float*)d_in[5];
    const int*   ridx   = (const int*)d_in[6];
    float* out = (float*)d_out;

    bias_kernel<<<(NT*NT + 255) / 256, 256>>>(table, ridx);

    const int gsmem = GEMM_SMEM_FLOATS * (int)sizeof(float);   // ~100 KB
    cudaFuncSetAttribute(gemm_tc<0>,
                         cudaFuncAttributeMaxDynamicSharedMemorySize, gsmem);
    cudaFuncSetAttribute(gemm_tc<1>,
                         cudaFuncAttributeMaxDynamicSharedMemorySize, gsmem);

    gemm_tc<0><<<dim3(576 / GBN, MROWS / GBM), 256, gsmem>>>(x, w_qkv, b_qkv, nullptr);

    const int asmem = AT_SMEM_FLOATS * (int)sizeof(float);     // ~207 KB
    cudaFuncSetAttribute(attn_tc_kernel,
                         cudaFuncAttributeMaxDynamicSharedMemorySize, asmem);
    attn_tc_kernel<<<B_ * NH, 256, asmem>>>();

    gemm_tc<1><<<dim3(CDIM / GBN, MROWS / GBM), 256, gsmem>>>(nullptr, w_proj, b_proj, out);
}

// round 17
// speedup vs baseline: 1.2109x; 1.2109x over previous
#include <cuda_runtime.h>
#include <mma.h>
#include <math.h>

using namespace nvcuda;

#define B_    256
#define NH    6
#define NT    343
#define NTP   352               // 343 padded to 22*16
#define HD    32
#define CDIM  192
#define MROWS (B_*NT)           // 87808 = 686*128
#define QSCALE 0.17677669529663687f

// ---------------- scratch (device globals; no allocation allowed) -----------
__device__ float g_q[(size_t)B_*NH*NT*HD];
__device__ float g_k[(size_t)B_*NH*NT*HD];
__device__ float g_v[(size_t)B_*NH*NT*HD];
__device__ float g_ao[(size_t)MROWS*CDIM];
__device__ float g_bias[(size_t)NH*NT*NT];

// ---------------- bias materialization --------------------------------------
__global__ void bias_kernel(const float* __restrict__ table,
                            const int*   __restrict__ ridx) {
    int i = blockIdx.x * blockDim.x + threadIdx.x;
    if (i >= NT*NT) return;
    int idx = ridx[i];
    #pragma unroll
    for (int h = 0; h < NH; h++)
        g_bias[(size_t)h*NT*NT + i] = table[idx*NH + h];
}

// ---------------- FFMA SGEMM (proven: 151us proj / ~460us qkv) --------------
#define BM 128
#define BN 64
#define BK 16
#define ASTR 132
#define BSTR 68

template<int MODE>
__global__ void __launch_bounds__(256)
gemm_kernel(const float* __restrict__ A_in,
            const float* __restrict__ W,
            const float* __restrict__ bias,
            float*       __restrict__ out) {
    __shared__ __align__(16) float As[2][BK * ASTR];
    __shared__ __align__(16) float Bs[2][BK * BSTR];
    const float* __restrict__ A = (MODE == 0) ? A_in : g_ao;
    const int t  = threadIdx.x;
    const int m0 = blockIdx.y * BM;
    const int n0 = blockIdx.x * BN;
    const int tx = t & 15;
    const int ty = t >> 4;
    const int lrow = t >> 2;
    const int lk4  = (t & 3) * 4;

    const float* pa0 = &A[(size_t)(m0 + lrow)      * CDIM + lk4];
    const float* pa1 = &A[(size_t)(m0 + lrow + 64) * CDIM + lk4];
    const float* pw  = &W[(size_t)(n0 + lrow)      * CDIM + lk4];

    float acc[8][4] = {};

    {
        float4 a0 = *(const float4*)pa0;
        float4 a1 = *(const float4*)pa1;
        float4 wv = *(const float4*)pw;
        As[0][(lk4+0)*ASTR + lrow] = a0.x; As[0][(lk4+1)*ASTR + lrow] = a0.y;
        As[0][(lk4+2)*ASTR + lrow] = a0.z; As[0][(lk4+3)*ASTR + lrow] = a0.w;
        As[0][(lk4+0)*ASTR + lrow + 64] = a1.x; As[0][(lk4+1)*ASTR + lrow + 64] = a1.y;
        As[0][(lk4+2)*ASTR + lrow + 64] = a1.z; As[0][(lk4+3)*ASTR + lrow + 64] = a1.w;
        Bs[0][(lk4+0)*BSTR + lrow] = wv.x; Bs[0][(lk4+1)*BSTR + lrow] = wv.y;
        Bs[0][(lk4+2)*BSTR + lrow] = wv.z; Bs[0][(lk4+3)*BSTR + lrow] = wv.w;
    }
    __syncthreads();

    int stage = 0;
    for (int k0 = 0; k0 < CDIM; k0 += BK) {
        float4 na0, na1, nwv;
        const bool has_next = (k0 + BK < CDIM);
        if (has_next) {
            na0 = *(const float4*)(pa0 + k0 + BK);
            na1 = *(const float4*)(pa1 + k0 + BK);
            nwv = *(const float4*)(pw  + k0 + BK);
        }
        const float* as = As[stage];
        const float* bs = Bs[stage];
        #pragma unroll
        for (int kk = 0; kk < BK; kk++) {
            float4 av0 = *(const float4*)&as[kk*ASTR + ty*8];
            float4 av1 = *(const float4*)&as[kk*ASTR + ty*8 + 4];
            float4 bv  = *(const float4*)&bs[kk*BSTR + tx*4];
            float a[8] = {av0.x, av0.y, av0.z, av0.w, av1.x, av1.y, av1.z, av1.w};
            float b[4] = {bv.x, bv.y, bv.z, bv.w};
            #pragma unroll
            for (int i = 0; i < 8; i++)
                #pragma unroll
                for (int j = 0; j < 4; j++)
                    acc[i][j] += a[i] * b[j];
        }
        if (has_next) {
            const int ns = stage ^ 1;
            As[ns][(lk4+0)*ASTR + lrow] = na0.x; As[ns][(lk4+1)*ASTR + lrow] = na0.y;
            As[ns][(lk4+2)*ASTR + lrow] = na0.z; As[ns][(lk4+3)*ASTR + lrow] = na0.w;
            As[ns][(lk4+0)*ASTR + lrow + 64] = na1.x; As[ns][(lk4+1)*ASTR + lrow + 64] = na1.y;
            As[ns][(lk4+2)*ASTR + lrow + 64] = na1.z; As[ns][(lk4+3)*ASTR + lrow + 64] = na1.w;
            Bs[ns][(lk4+0)*BSTR + lrow] = nwv.x; Bs[ns][(lk4+1)*BSTR + lrow] = nwv.y;
            Bs[ns][(lk4+2)*BSTR + lrow] = nwv.z; Bs[ns][(lk4+3)*BSTR + lrow] = nwv.w;
            __syncthreads();
        }
        stage ^= 1;
    }

    #pragma unroll
    for (int i = 0; i < 8; i++) {
        int m = m0 + ty * 8 + i;
        #pragma unroll
        for (int j = 0; j < 4; j++) {
            int c = n0 + tx * 4 + j;
            float v = acc[i][j] + bias[c];
            if (MODE == 0) {
                int b = m / NT, n = m - b * NT;
                int s = c / CDIM;
                int hc = c - s * CDIM;
                int h = hc >> 5, d = hc & 31;
                size_t dst = ((size_t)(b * NH + h) * NT + n) * HD + d;
                if      (s == 0) g_q[dst] = v * QSCALE;
                else if (s == 1) g_k[dst] = v;
                else             g_v[dst] = v;
            } else {
                out[(size_t)m * CDIM + c] = v;
            }
        }
    }
}

// ---------------- attention: tf32 WMMA, one CTA per (b,h) -------------------
// tf32 conversion hoisted to data STORES (staging of Q/K/V, softmax write of
// P): numerically identical to per-fragment CVT, ~450 fewer issue slots per
// thread per query-block.
#define KS2 36
#define SST 356
#define QB  64
#define AT_SMEM_FLOATS (2*NTP*KS2 + QB*SST + QB*KS2 + 8*16*20)

__device__ __forceinline__ float4 cvt4(float4 v) {
    v.x = wmma::__float_to_tf32(v.x);
    v.y = wmma::__float_to_tf32(v.y);
    v.z = wmma::__float_to_tf32(v.z);
    v.w = wmma::__float_to_tf32(v.w);
    return v;
}

__global__ void __launch_bounds__(256) attn_tc_kernel() {
    extern __shared__ float sm[];
    float* ks = sm;                       // [NTP][KS2]  (tf32 values)
    float* vs = ks + NTP * KS2;           // [NTP][KS2]  (tf32 values)
    float* ss = vs + NTP * KS2;           // [QB][SST]   (scores f32 -> P tf32)
    float* qs = ss + QB * SST;            // [QB][KS2]   (tf32 values)
    float* os = qs + QB * KS2;            // [8][320]

    const int bh = blockIdx.x;            // 0..1535
    const int b  = bh / NH, h = bh % NH;
    const size_t base = (size_t)bh * NT * HD;
    const int t = threadIdx.x, warp = t >> 5, lane = t & 31;

    for (int i = t; i < (NTP - NT) * KS2; i += 256) {
        int r = NT + i / KS2, c = i % KS2;
        ks[r * KS2 + c] = 0.f;
        vs[r * KS2 + c] = 0.f;
    }
    for (int i = t; i < NT * HD / 4; i += 256) {
        int e = i * 4;
        int j = e >> 5, d = e & 31;
        *(float4*)&ks[j * KS2 + d] = cvt4(*(const float4*)&g_k[base + e]);
        *(float4*)&vs[j * KS2 + d] = cvt4(*(const float4*)&g_v[base + e]);
    }
    __syncthreads();

    const float* __restrict__ bm = &g_bias[(size_t)h * NT * NT];

    for (int qb = 0; qb < NT; qb += QB) {
        for (int i = t; i < QB * HD / 4; i += 256) {
            int e = i * 4;
            int r = e >> 5, d = e & 31;
            int gr = qb + r;
            float4 v = (gr < NT)
                ? cvt4(*(const float4*)&g_q[base + (size_t)gr * HD + d])
                : make_float4(0.f, 0.f, 0.f, 0.f);
            *(float4*)&qs[r * KS2 + d] = v;
        }
        __syncthreads();

        // ---- S = Q @ K^T (operands already tf32 in smem; no per-frag cvt) ----
        {
            int rt = warp & 3;
            int c0 = (warp >> 2) * 11;
            wmma::fragment<wmma::matrix_a, 16, 16, 8, wmma::precision::tf32,
                           wmma::row_major> a[4];
            #pragma unroll
            for (int kk = 0; kk < 4; kk++)
                wmma::load_matrix_sync(a[kk], &qs[rt * 16 * KS2 + kk * 8], KS2);
            for (int ct = c0; ct < c0 + 11; ct++) {
                wmma::fragment<wmma::accumulator, 16, 16, 8, float> acc;
                wmma::fill_fragment(acc, 0.0f);
                #pragma unroll
                for (int kk = 0; kk < 4; kk++) {
                    wmma::fragment<wmma::matrix_b, 16, 16, 8, wmma::precision::tf32,
                                   wmma::col_major> bf;
                    wmma::load_matrix_sync(bf, &ks[ct * 16 * KS2 + kk * 8], KS2);
                    wmma::mma_sync(acc, a[kk], bf, acc);
                }
                wmma::store_matrix_sync(&ss[rt * 16 * SST + ct * 16], acc, SST,
                                        wmma::mem_row_major);
            }
        }
        __syncthreads();

        // ---- softmax rows (writes P as tf32 values) ----
        for (int rl = warp * 8; rl < warp * 8 + 8; rl++) {
            int r = qb + rl;
            if (r >= NT) break;
            float* srow = &ss[rl * SST];
            const float* brow = &bm[(size_t)r * NT];
            float v[11];
            float mx = -1e30f;
            #pragma unroll
            for (int tt = 0; tt < 11; tt++) {
                int j = tt * 32 + lane;
                float s = (j < NT) ? srow[j] + brow[j] : -1e30f;
                v[tt] = s;
                mx = fmaxf(mx, s);
            }
            #pragma unroll
            for (int o = 16; o; o >>= 1)
                mx = fmaxf(mx, __shfl_xor_sync(0xffffffffu, mx, o));
            float sum = 0.f;
            #pragma unroll
            for (int tt = 0; tt < 11; tt++) {
                int j = tt * 32 + lane;
                if (j < NT) { float e = __expf(v[tt] - mx); v[tt] = e; sum += e; }
                else v[tt] = 0.f;
            }
            #pragma unroll
            for (int o = 16; o; o >>= 1)
                sum += __shfl_xor_sync(0xffffffffu, sum, o);
            float inv = __frcp_rn(sum);
            #pragma unroll
            for (int tt = 0; tt < 11; tt++) {
                int j = tt * 32 + lane;
                srow[j] = wmma::__float_to_tf32(v[tt] * inv);
            }
        }
        __syncthreads();

        // ---- O = P @ V (operands already tf32; two accs for ILP) ----
        {
            int rt = warp & 3, ct = warp >> 2;
            wmma::fragment<wmma::accumulator, 16, 16, 8, float> acc0, acc1;
            wmma::fill_fragment(acc0, 0.0f);
            wmma::fill_fragment(acc1, 0.0f);
            #pragma unroll 4
            for (int kk = 0; kk < NTP / 8; kk += 2) {
                wmma::fragment<wmma::matrix_a, 16, 16, 8, wmma::precision::tf32,
                               wmma::row_major> pa, pb;
                wmma::fragment<wmma::matrix_b, 16, 16, 8, wmma::precision::tf32,
                               wmma::row_major> va, vb;
                wmma::load_matrix_sync(pa, &ss[rt * 16 * SST + kk * 8], SST);
                wmma::load_matrix_sync(va, &vs[kk * 8 * KS2 + ct * 16], KS2);
                wmma::mma_sync(acc0, pa, va, acc0);
                wmma::load_matrix_sync(pb, &ss[rt * 16 * SST + (kk + 1) * 8], SST);
                wmma::load_matrix_sync(vb, &vs[(kk + 1) * 8 * KS2 + ct * 16], KS2);
                wmma::mma_sync(acc1, pb, vb, acc1);
            }
            #pragma unroll
            for (int e = 0; e < acc0.num_elements; e++)
                acc0.x[e] += acc1.x[e];
            wmma::store_matrix_sync(&os[warp * 320], acc0, 20, wmma::mem_row_major);
            __syncwarp();
            #pragma unroll
            for (int e = 0; e < 8; e++) {
                int idx = lane * 8 + e;
                int row = idx >> 4, col = idx & 15;
                int r = qb + rt * 16 + row;
                if (r < NT)
                    g_ao[((size_t)b * NT + r) * CDIM + h * HD + ct * 16 + col] =
                        os[warp * 320 + row * 20 + col];
            }
        }
        __syncthreads();
    }
}

// ---------------- launch ----------------------------------------------------
extern "C" void kernel_launch(void* const* d_in, const int* in_sizes, int n_in,
                              void* d_out, int out_size) {
    const float* x      = (const float*)d_in[0];
    const float* w_qkv  = (const float*)d_in[1];
    const float* b_qkv  = (const float*)d_in[2];
    const float* w_proj = (const float*)d_in[3];
    const float* b_proj = (const float*)d_in[4];
    const float* table  = (const float*)d_in[5];
    const int*   ridx   = (const int*)d_in[6];
    float* out = (float*)d_out;

    bias_kernel<<<(NT*NT + 255) / 256, 256>>>(table, ridx);

    gemm_kernel<0><<<dim3(576 / BN, MROWS / BM), 256>>>(x, w_qkv, b_qkv, nullptr);

    const int asmem = AT_SMEM_FLOATS * (int)sizeof(float);     // ~207 KB
    cudaFuncSetAttribute(attn_tc_kernel,
                         cudaFuncAttributeMaxDynamicSharedMemorySize, asmem);
    attn_tc_kernel<<<B_ * NH, 256, asmem>>>();

    gemm_kernel<1><<<dim3(CDIM / BN, MROWS / BM), 256>>>(nullptr, w_proj, b_proj, out);
}